// round 8
// baseline (speedup 1.0000x reference)
#include <cuda_runtime.h>
#include <cuda_bf16.h>
#include <cstdint>

// BFPActivation3D: block floating-point quantization over channel blocks.
// Shapes (fixed): activations [N=8, C=64, D=32, H=64, W=64] fp32,
// mantissa = 7, blk = 16. Blocks run along C at stride S = D*H*W.
//
// Per block of 16 channel values x_c at one spatial position:
//   maxabs = max |x_c|
//   se     = floor(log2(maxabs))            (== frexp exponent - 1)
//   quantum = 2^(se-6);  q_c = clip(rint(x_c/quantum), -127, 127) * quantum
//   all-zero block -> 0
// Power-of-two scales are exact; rintf = half-to-even = jnp.round.
// rel_err == 0.0 verified on hardware (R5, R7).
//
// R7 post-mortem: float4 tile (80 regs, 3 CTAs/SM) left DRAM at 81.6%.
// This round: float2 tile -> 32 data regs, <=64 total, 4 CTAs/SM (32 warps,
// the exact 64K-reg RF boundary), and each warp LDG.64 covers a 256B segment
// (nL=2) for finer read/write interleave at the L1tex wavefront queue.

namespace {
constexpr int N_      = 8;
constexpr int C_      = 64;
constexpr int S_      = 32 * 64 * 64;   // D*H*W = 131072
constexpr int BLK     = 16;             // channels per block
constexpr int NBLK    = C_ / BLK;       // 4
constexpr int S2      = S_ / 2;         // float2 positions per (n, cblk) = 65536
constexpr int THREADS = 256;
constexpr int TOTAL_T = N_ * NBLK * S2; // 2,097,152 threads
}

__global__ __launch_bounds__(THREADS, 4)
void bfp3d_kernel(const float* __restrict__ in, float* __restrict__ out) {
    const int t = blockIdx.x * THREADS + threadIdx.x;
    // t -> (n, cblk, s2). S2 = 2^16, NBLK = 4.
    const int s2   = t & (S2 - 1);
    const int cblk = (t >> 16) & (NBLK - 1);
    const int n    = t >> 18;

    const int base = (n * C_ + cblk * BLK) * S_ + s2 * 2;   // < 2^27, int ok
    const float2* __restrict__ ip = reinterpret_cast<const float2*>(in + base);
    float2* __restrict__ op = reinterpret_cast<float2*>(out + base);

    // 16 strided float2 loads; across a warp each is a contiguous 256B segment.
    // Streaming (evict-first): data is touched exactly once.
    float x[2][BLK];   // [position within float2][channel]
    #pragma unroll
    for (int c = 0; c < BLK; c++) {
        float2 v = __ldcs(ip + c * S2);
        x[0][c] = v.x; x[1][c] = v.y;
    }

    #pragma unroll
    for (int l = 0; l < 2; l++) {
        float m = fabsf(x[l][0]);
        #pragma unroll
        for (int c = 1; c < BLK; c++) m = fmaxf(m, fabsf(x[l][c]));

        // shared exponent = floor(log2(m)) for normal m
        const int se = (int)((__float_as_uint(m) >> 23) & 0xFFu) - 127;

        // exact power-of-two scales (integer exponent -> exact construction)
        const float rscale  = ldexpf(1.0f, 6 - se);   // 1/quantum
        const float quantum = ldexpf(1.0f, se - 6);

        const bool nz = (m > 0.0f);
        #pragma unroll
        for (int c = 0; c < BLK; c++) {
            float q = rintf(x[l][c] * rscale);          // half-to-even
            q = fminf(fmaxf(q, -127.0f), 127.0f);
            q *= quantum;
            x[l][c] = nz ? q : 0.0f;
        }
    }

    #pragma unroll
    for (int c = 0; c < BLK; c++) {
        float2 v;
        v.x = x[0][c]; v.y = x[1][c];
        __stcs(op + c * S2, v);   // streaming store: no reuse, evict first
    }
}

extern "C" void kernel_launch(void* const* d_in, const int* in_sizes, int n_in,
                              void* d_out, int out_size) {
    const float* in = (const float*)d_in[0];   // activations, 67,108,864 floats
    float* out = (float*)d_out;
    (void)in_sizes; (void)n_in; (void)out_size;   // mantissa=7, blk=16 fixed

    bfp3d_kernel<<<TOTAL_T / THREADS, THREADS>>>(in, out);
}